// round 12
// baseline (speedup 1.0000x reference)
#include <cuda_runtime.h>
#include <math.h>
#include <string.h>

#define NB    2
#define NCAM  6
#define DIM   256
#define HWQ   2500
#define PK    625
#define PKP   628
#define NHEAD 8
#define DH    32
#define ND    1536

typedef unsigned long long u64;

__device__ __forceinline__ u64 ffma2(u64 a, u64 b, u64 c){
    u64 d; asm("fma.rn.f32x2 %0, %1, %2, %3;" : "=l"(d) : "l"(a), "l"(b), "l"(c)); return d;
}
__device__ __forceinline__ u64 pack2(float x, float y){
    u64 d; asm("mov.b64 %0, {%1, %2};" : "=l"(d) : "f"(x), "f"(y)); return d;
}
__device__ __forceinline__ float2 unpack2(u64 v){
    float2 r; asm("mov.b64 {%0, %1}, %2;" : "=f"(r.x), "=f"(r.y) : "l"(v)); return r;
}

__device__ float g_kpool [(long)NB*NCAM*DIM*PKP];
__device__ float g_vpool [(long)NB*NCAM*DIM*PKP];
__device__ float g_qf    [(long)NB*NCAM*HWQ*DIM];
__device__ float g_kf    [(long)NB*NCAM*PK*DIM];
__device__ float g_vf    [(long)NB*NCAM*PK*DIM];
__device__ float g_attno [(long)NB*HWQ*ND];
__device__ float g_fac   [(long)NB*HWQ*48];
__device__ float g_lnbuf [(long)NB*HWQ*ND];
__device__ float g_xbuf  [(long)NB*HWQ*DIM];
__device__ float g_h1    [(long)NB*HWQ*2*DIM];
__device__ float g_part1 [(long)3*NB*HWQ*DIM];
__device__ float g_part2 [(long)3*NB*HWQ*DIM];
__device__ float g_part3 [(long)2*NB*HWQ*DIM];

__device__ __forceinline__ float warpRedSum(float v){
    #pragma unroll
    for (int o=16;o;o>>=1) v += __shfl_xor_sync(0xffffffffu, v, o);
    return v;
}

// ---- 2x2 pool, natural (b,cam,c,kk) output with padded k-stride ----
__global__ void pool_kernel(const float* __restrict__ src, float* __restrict__ dst){
    long idx = (long)blockIdx.x * blockDim.x + threadIdx.x;
    const long total = (long)NB*NCAM*DIM*PK;
    if (idx >= total) return;
    int kk  = (int)(idx % PK);  long t = idx / PK;
    int c   = (int)(t % DIM);   t /= DIM;
    int cam = (int)(t % NCAM);
    int b   = (int)(t / NCAM);
    int i = kk / 25, j = kk % 25;
    const float* p = src + ((long)((b*NCAM+cam)*DIM + c))*HWQ + (2*i)*50 + 2*j;
    float v = 0.25f * (p[0] + p[1] + p[50] + p[51]);
    dst[((long)((b*NCAM+cam)*DIM + c))*PKP + kk] = v;
}

struct GemmP {
    const float* A; const float* B; const float* bias; float* C;
    int lda, ldb, ldc;
    int M, N, K;
    int gelu, D1, SPLIT, ATR;
    long a0, a1, c0, c1, csplit;
};

__global__ __launch_bounds__(128,4) void gemm_tc(GemmP p){
    __shared__ float As[2][16][128];
    __shared__ float Bs[2][16][64];

    int z = blockIdx.z;
    int s = z % p.SPLIT; int zz = z / p.SPLIT;
    int i1 = zz % p.D1;  int i0 = zz / p.D1;
    long askip = (long)s*p.K*(p.ATR ? (long)p.lda : 1L);
    const float* A = p.A + i0*p.a0 + i1*p.a1 + askip;
    const float* B = p.B + (long)s*p.K*p.ldb;
    float*       C = p.C + i0*p.c0 + i1*p.c1 + (long)s*p.csplit;

    int tid = threadIdx.x;
    int tx = tid & 7, ty = tid >> 3;
    int row0 = blockIdx.y*128, col0 = blockIdx.x*64;

    int arow = row0 + tid;
    bool aok = arow < p.M;
    int brow = tid >> 3;
    int bc0  = (tid & 7) * 2;
    int pb0  = (bc0 ^ (bc0 >> 3)) * 4;
    int pb1  = ((bc0+1) ^ ((bc0+1) >> 3)) * 4;

    u64 acc[8][4];
    #pragma unroll
    for (int i=0;i<8;i++)
        #pragma unroll
        for (int j=0;j<4;j++) acc[i][j] = 0ULL;

    const float4 z4 = make_float4(0.f,0.f,0.f,0.f);
    float av[16]; float4 rb0, rb1;
    const float* atc = p.ATR ? (A + arow) : (A + (aok ? (long)arow*p.lda : 0));

    int nt = p.K / 16;
    if (!p.ATR){
        if (aok){
            float4 r0=*(const float4*)atc, r1=*(const float4*)(atc+4);
            float4 r2=*(const float4*)(atc+8), r3=*(const float4*)(atc+12);
            av[0]=r0.x;av[1]=r0.y;av[2]=r0.z;av[3]=r0.w;
            av[4]=r1.x;av[5]=r1.y;av[6]=r1.z;av[7]=r1.w;
            av[8]=r2.x;av[9]=r2.y;av[10]=r2.z;av[11]=r2.w;
            av[12]=r3.x;av[13]=r3.y;av[14]=r3.z;av[15]=r3.w;
        } else {
            #pragma unroll
            for (int j=0;j<16;j++) av[j]=0.f;
        }
    } else {
        #pragma unroll
        for (int j=0;j<16;j++) av[j] = aok ? atc[(long)j*p.lda] : 0.f;
    }
    {
        const float* pb = B + (long)brow*p.ldb + col0 + bc0*4;
        rb0 = *(const float4*)pb; rb1 = *(const float4*)(pb+4);
    }
    {
        #pragma unroll
        for (int j=0;j<16;j++) As[0][j][tid]=av[j];
        *(float4*)&Bs[0][brow][pb0] = rb0;
        *(float4*)&Bs[0][brow][pb1] = rb1;
    }
    __syncthreads();
    int cur = 0;
    for (int t=0; t<nt; t++){
        if (t+1 < nt){
            int k0 = (t+1)*16;
            if (!p.ATR){
                if (aok){
                    const float* pa = atc + k0;
                    float4 r0=*(const float4*)pa, r1=*(const float4*)(pa+4);
                    float4 r2=*(const float4*)(pa+8), r3=*(const float4*)(pa+12);
                    av[0]=r0.x;av[1]=r0.y;av[2]=r0.z;av[3]=r0.w;
                    av[4]=r1.x;av[5]=r1.y;av[6]=r1.z;av[7]=r1.w;
                    av[8]=r2.x;av[9]=r2.y;av[10]=r2.z;av[11]=r2.w;
                    av[12]=r3.x;av[13]=r3.y;av[14]=r3.z;av[15]=r3.w;
                }
            } else {
                #pragma unroll
                for (int j=0;j<16;j++) av[j] = aok ? atc[(long)(k0+j)*p.lda] : 0.f;
            }
            const float* pb = B + (long)(k0+brow)*p.ldb + col0 + bc0*4;
            rb0 = *(const float4*)pb; rb1 = *(const float4*)(pb+4);
        }
        #pragma unroll
        for (int kk=0; kk<16; kk++){
            float4 a0 = *(const float4*)&As[cur][kk][ty*8];
            float4 a1 = *(const float4*)&As[cur][kk][ty*8+4];
            ulonglong2 b0 = *(const ulonglong2*)&Bs[cur][kk][pb0];
            ulonglong2 b1 = *(const ulonglong2*)&Bs[cur][kk][pb1];
            u64 ap;
            ap=pack2(a0.x,a0.x); acc[0][0]=ffma2(ap,b0.x,acc[0][0]); acc[0][1]=ffma2(ap,b0.y,acc[0][1]); acc[0][2]=ffma2(ap,b1.x,acc[0][2]); acc[0][3]=ffma2(ap,b1.y,acc[0][3]);
            ap=pack2(a0.y,a0.y); acc[1][0]=ffma2(ap,b0.x,acc[1][0]); acc[1][1]=ffma2(ap,b0.y,acc[1][1]); acc[1][2]=ffma2(ap,b1.x,acc[1][2]); acc[1][3]=ffma2(ap,b1.y,acc[1][3]);
            ap=pack2(a0.z,a0.z); acc[2][0]=ffma2(ap,b0.x,acc[2][0]); acc[2][1]=ffma2(ap,b0.y,acc[2][1]); acc[2][2]=ffma2(ap,b1.x,acc[2][2]); acc[2][3]=ffma2(ap,b1.y,acc[2][3]);
            ap=pack2(a0.w,a0.w); acc[3][0]=ffma2(ap,b0.x,acc[3][0]); acc[3][1]=ffma2(ap,b0.y,acc[3][1]); acc[3][2]=ffma2(ap,b1.x,acc[3][2]); acc[3][3]=ffma2(ap,b1.y,acc[3][3]);
            ap=pack2(a1.x,a1.x); acc[4][0]=ffma2(ap,b0.x,acc[4][0]); acc[4][1]=ffma2(ap,b0.y,acc[4][1]); acc[4][2]=ffma2(ap,b1.x,acc[4][2]); acc[4][3]=ffma2(ap,b1.y,acc[4][3]);
            ap=pack2(a1.y,a1.y); acc[5][0]=ffma2(ap,b0.x,acc[5][0]); acc[5][1]=ffma2(ap,b0.y,acc[5][1]); acc[5][2]=ffma2(ap,b1.x,acc[5][2]); acc[5][3]=ffma2(ap,b1.y,acc[5][3]);
            ap=pack2(a1.z,a1.z); acc[6][0]=ffma2(ap,b0.x,acc[6][0]); acc[6][1]=ffma2(ap,b0.y,acc[6][1]); acc[6][2]=ffma2(ap,b1.x,acc[6][2]); acc[6][3]=ffma2(ap,b1.y,acc[6][3]);
            ap=pack2(a1.w,a1.w); acc[7][0]=ffma2(ap,b0.x,acc[7][0]); acc[7][1]=ffma2(ap,b0.y,acc[7][1]); acc[7][2]=ffma2(ap,b1.x,acc[7][2]); acc[7][3]=ffma2(ap,b1.y,acc[7][3]);
        }
        if (t+1 < nt){
            int nb = cur ^ 1;
            #pragma unroll
            for (int j=0;j<16;j++) As[nb][j][tid]=av[j];
            *(float4*)&Bs[nb][brow][pb0] = rb0;
            *(float4*)&Bs[nb][brow][pb1] = rb1;
            __syncthreads();
            cur = nb;
        }
    }
    int colb = col0 + tx*8;
    float4 bia0, bia1;
    if (p.SPLIT == 1 && p.bias){
        bia0 = *(const float4*)(p.bias + colb);
        bia1 = *(const float4*)(p.bias + colb + 4);
    } else { bia0 = z4; bia1 = z4; }
    #pragma unroll
    for (int i=0;i<8;i++){
        int r = row0 + ty*8 + i;
        if (r >= p.M) continue;
        float2 v0 = unpack2(acc[i][0]), v1 = unpack2(acc[i][1]);
        float2 v2 = unpack2(acc[i][2]), v3 = unpack2(acc[i][3]);
        float4 o0 = make_float4(v0.x+bia0.x, v0.y+bia0.y, v1.x+bia0.z, v1.y+bia0.w);
        float4 o1 = make_float4(v2.x+bia1.x, v2.y+bia1.y, v3.x+bia1.z, v3.y+bia1.w);
        if (p.gelu){
            o0.x*=normcdff(o0.x); o0.y*=normcdff(o0.y); o0.z*=normcdff(o0.z); o0.w*=normcdff(o0.w);
            o1.x*=normcdff(o1.x); o1.y*=normcdff(o1.y); o1.z*=normcdff(o1.z); o1.w*=normcdff(o1.w);
        }
        *(float4*)(C + (long)r*p.ldc + colb)     = o0;
        *(float4*)(C + (long)r*p.ldc + colb + 4) = o1;
    }
}

// ---- flash attention: per-(b,head,cam) blocks, q-tile 128, no max tracking ----
#define QS_OFF 0
#define KS_OFF 4096
#define VT_OFF 8704
#define PS_OFF 13056
#define FL_SMEM (21760*4)

__global__ __launch_bounds__(256,1) void flash_kernel(
    const float* __restrict__ qf, const float* __restrict__ kf,
    const float* __restrict__ vf, float* __restrict__ ao, float* __restrict__ fac)
{
    extern __shared__ float sm[];
    float* Qs    = sm + QS_OFF;
    float* KsB   = sm + KS_OFF;
    float* VtB   = sm + VT_OFF;
    float* Ps    = sm + PS_OFF;

    int yy = blockIdx.y;
    int cam = yy % 6; int bm = yy / 6; int b = bm >> 3, m = bm & 7;
    int q0 = blockIdx.x * 128;
    int tid = threadIdx.x;

    int kg = tid & 15, rg = tid >> 4;
    int rgx = (rg & 1) << 4;
    int ks = tid >> 7, low = tid & 127;
    int orow = low >> 3, oc = low & 7;
    int orx = (orow & 1) << 4;
    int qr = tid >> 1, qh = tid & 1;
    int fr = tid >> 2, fq = tid & 3;

    const float scale = 0.17677669529663689f;
    const float4 z4 = make_float4(0.f,0.f,0.f,0.f);

    const float* qb = qf + ((long)(b*NCAM+cam)*HWQ)*DIM + m*DH;
    const float* kb = kf + ((long)(b*NCAM+cam)*PK)*DIM + m*DH;
    const float* vb = vf + ((long)(b*NCAM+cam)*PK)*DIM + m*DH;

    {
        bool qok = (q0 + qr) < HWQ;
        const float* qp = qb + (long)(q0+qr)*DIM + qh*16;
        float4 q0r = qok ? *(const float4*)(qp)     : z4;
        float4 q1r = qok ? *(const float4*)(qp + 4) : z4;
        float4 q2r = qok ? *(const float4*)(qp + 8) : z4;
        float4 q3r = qok ? *(const float4*)(qp +12) : z4;
        float4 kr0 = *(const float4*)(kb + (long)fr*DIM + fq*8);
        float4 kr1 = *(const float4*)(kb + (long)fr*DIM + fq*8 + 4);
        float4 vr0 = *(const float4*)(vb + (long)fr*DIM + fq*8);
        float4 vr1 = *(const float4*)(vb + (long)fr*DIM + fq*8 + 4);
        int rl = qr & 7;
        q0r.x*=scale; q0r.y*=scale; q0r.z*=scale; q0r.w*=scale;
        q1r.x*=scale; q1r.y*=scale; q1r.z*=scale; q1r.w*=scale;
        q2r.x*=scale; q2r.y*=scale; q2r.z*=scale; q2r.w*=scale;
        q3r.x*=scale; q3r.y*=scale; q3r.z*=scale; q3r.w*=scale;
        *(float4*)(Qs + qr*32 + (((qh*4+0)^rl)<<2)) = q0r;
        *(float4*)(Qs + qr*32 + (((qh*4+1)^rl)<<2)) = q1r;
        *(float4*)(Qs + qr*32 + (((qh*4+2)^rl)<<2)) = q2r;
        *(float4*)(Qs + qr*32 + (((qh*4+3)^rl)<<2)) = q3r;
        *(float4*)(KsB + fr*36 + fq*8)     = kr0;
        *(float4*)(KsB + fr*36 + fq*8 + 4) = kr1;
        VtB[(fq*8+0)*68 + fr] = vr0.x; VtB[(fq*8+1)*68 + fr] = vr0.y;
        VtB[(fq*8+2)*68 + fr] = vr0.z; VtB[(fq*8+3)*68 + fr] = vr0.w;
        VtB[(fq*8+4)*68 + fr] = vr1.x; VtB[(fq*8+5)*68 + fr] = vr1.y;
        VtB[(fq*8+6)*68 + fr] = vr1.z; VtB[(fq*8+7)*68 + fr] = vr1.w;
    }
    __syncthreads();

    float lrow[8];
    #pragma unroll
    for (int i=0;i<8;i++) lrow[i] = 0.f;
    u64 acc[8][4];
    #pragma unroll
    for (int i=0;i<8;i++)
        #pragma unroll
        for (int s=0;s<4;s++) acc[i][s] = 0ULL;

    float4 kr0, kr1, vr0, vr1;
    for (int kt=0; kt<10; kt++){
        int cur = kt & 1;
        if (kt < 9){
            int kn = (kt+1)*64;
            bool ok = (kn + fr) < PK;
            const float* kp = kb + (long)(kn+fr)*DIM + fq*8;
            const float* vp = vb + (long)(kn+fr)*DIM + fq*8;
            kr0 = ok ? *(const float4*)kp     : z4;
            kr1 = ok ? *(const float4*)(kp+4) : z4;
            vr0 = ok ? *(const float4*)vp     : z4;
            vr1 = ok ? *(const float4*)(vp+4) : z4;
        }
        u64 sacc[8][4];
        #pragma unroll
        for (int i=0;i<8;i++)
            #pragma unroll
            for (int j=0;j<4;j++) sacc[i][j] = 0ULL;
        const float* Kc = KsB + cur*2304;
        #pragma unroll
        for (int c4=0;c4<8;c4++){
            ulonglong2 kv[4];
            #pragma unroll
            for (int j=0;j<4;j++)
                kv[j] = *(const ulonglong2*)(Kc + (kg+16*j)*36 + c4*4);
            #pragma unroll
            for (int i=0;i<8;i++){
                ulonglong2 qv = *(const ulonglong2*)(Qs + (rg*8+i)*32 + ((c4 ^ i)<<2));
                #pragma unroll
                for (int j=0;j<4;j++){
                    sacc[i][j] = ffma2(qv.x, kv[j].x, sacc[i][j]);
                    sacc[i][j] = ffma2(qv.y, kv[j].y, sacc[i][j]);
                }
            }
        }
        int kk0 = kt*64;
        #pragma unroll
        for (int i=0;i<8;i++){
            float rsum = 0.f;
            #pragma unroll
            for (int j=0;j<4;j++){
                float2 t2 = unpack2(sacc[i][j]);
                float pv = (kk0 + kg + 16*j < PK) ? __expf(t2.x + t2.y) : 0.f;
                rsum += pv;
                Ps[(rg*8+i)*68 + ((kg + 16*j) ^ rgx)] = pv;
            }
            #pragma unroll
            for (int off=1; off<16; off<<=1)
                rsum += __shfl_xor_sync(0xffffffffu, rsum, off);
            lrow[i] += rsum;
        }
        __syncthreads();
        const float* Vc = VtB + cur*2176;
        #pragma unroll
        for (int t=0;t<8;t++){
            int k4 = (ks*8 + t)*4;
            ulonglong2 vv[4];
            #pragma unroll
            for (int s=0;s<4;s++)
                vv[s] = *(const ulonglong2*)(Vc + (oc+8*s)*68 + k4);
            #pragma unroll
            for (int i=0;i<8;i++){
                ulonglong2 pp = *(const ulonglong2*)(Ps + (orow*8+i)*68 + (k4 ^ orx));
                #pragma unroll
                for (int s=0;s<4;s++){
                    acc[i][s] = ffma2(pp.x, vv[s].x, acc[i][s]);
                    acc[i][s] = ffma2(pp.y, vv[s].y, acc[i][s]);
                }
            }
        }
        if (kt < 9){
            int nb = cur ^ 1;
            *(float4*)(KsB + nb*2304 + fr*36 + fq*8)     = kr0;
            *(float4*)(KsB + nb*2304 + fr*36 + fq*8 + 4) = kr1;
            float* Vn = VtB + nb*2176;
            Vn[(fq*8+0)*68 + fr] = vr0.x; Vn[(fq*8+1)*68 + fr] = vr0.y;
            Vn[(fq*8+2)*68 + fr] = vr0.z; Vn[(fq*8+3)*68 + fr] = vr0.w;
            Vn[(fq*8+4)*68 + fr] = vr1.x; Vn[(fq*8+5)*68 + fr] = vr1.y;
            Vn[(fq*8+6)*68 + fr] = vr1.z; Vn[(fq*8+7)*68 + fr] = vr1.w;
        }
        __syncthreads();
    }

    float o[8][4];
    #pragma unroll
    for (int i=0;i<8;i++)
        #pragma unroll
        for (int s=0;s<4;s++){
            float2 t = unpack2(acc[i][s]);
            o[i][s] = t.x + t.y;
        }
    if (ks == 1){
        #pragma unroll
        for (int i=0;i<8;i++)
            #pragma unroll
            for (int s=0;s<4;s++)
                Ps[(orow*8+i)*33 + oc + 8*s] = o[i][s];
    }
    __syncthreads();
    if (ks == 0){
        #pragma unroll
        for (int i=0;i<8;i++){
            int qq = q0 + orow*8 + i;
            if (qq >= HWQ) continue;
            long base = ((long)b*HWQ + qq)*ND + cam*DIM + m*DH;
            #pragma unroll
            for (int s=0;s<4;s++)
                ao[base + oc + 8*s] = o[i][s] + Ps[(orow*8+i)*33 + oc + 8*s];
        }
    }
    if (kg == 0){
        #pragma unroll
        for (int i=0;i<8;i++){
            int qq = q0 + rg*8 + i;
            if (qq >= HWQ) continue;
            fac[((long)b*HWQ + qq)*48 + cam*8 + m] = lrow[i];
        }
    }
}

__global__ void ln1536_kernel(const float* __restrict__ x, const float* __restrict__ fac,
                              const float* __restrict__ g, const float* __restrict__ b,
                              float* __restrict__ y){
    __shared__ float sh[8];
    __shared__ float bmu, brs;
    __shared__ float f8[8];
    long row = blockIdx.x;
    const float* p = x + row * (long)ND;
    const float* fr = fac + row * 48;
    int tid = threadIdx.x;
    if (tid < 8){
        float den = 0.f;
        #pragma unroll
        for (int c=0;c<6;c++) den += fr[c*8+tid];
        f8[tid] = 1.f / den;
    }
    __syncthreads();
    float vals[6]; float s = 0.f;
    #pragma unroll
    for (int i=0;i<6;i++){
        int c = tid + i*256;
        vals[i] = p[c] * f8[(c>>5)&7]; s += vals[i];
    }
    s = warpRedSum(s);
    if ((tid & 31) == 0) sh[tid>>5] = s;
    __syncthreads();
    if (tid == 0){ float t=0.f; for (int i=0;i<8;i++) t += sh[i]; bmu = t / (float)ND; }
    __syncthreads();
    float mu = bmu, vs = 0.f;
    #pragma unroll
    for (int i=0;i<6;i++){ float d = vals[i]-mu; vs += d*d; }
    vs = warpRedSum(vs);
    if ((tid & 31) == 0) sh[tid>>5] = vs;
    __syncthreads();
    if (tid == 0){ float t=0.f; for (int i=0;i<8;i++) t += sh[i]; brs = rsqrtf(t/(float)ND + 1e-5f); }
    __syncthreads();
    float rs = brs;
    float* q = y + row * (long)ND;
    #pragma unroll
    for (int i=0;i<6;i++){ int c = tid + i*256; q[c] = (vals[i]-mu)*rs*g[c] + b[c]; }
}

__global__ void reduce_proj_kernel(const float* __restrict__ p1, const float* __restrict__ p2,
                                   const float* __restrict__ baddq, const float* __restrict__ bproj,
                                   float* __restrict__ xb){
    long idx = (long)blockIdx.x * 256 + threadIdx.x;
    const long MN = (long)NB*HWQ*DIM;
    if (idx >= MN) return;
    int c = (int)(idx & 255);
    float v = bproj[c] + baddq[c];
    v += p1[idx] + p1[idx+MN] + p1[idx+2*MN];
    v += p2[idx] + p2[idx+MN] + p2[idx+2*MN];
    xb[idx] = v;
}

// ---- final: LN(sum p3 + b2) + x, direct transposed store (L2-coalescing) ----
__global__ void final_kernel(const float* __restrict__ p3, const float* __restrict__ b2,
                             const float* __restrict__ x,
                             const float* __restrict__ g, const float* __restrict__ bb,
                             float* __restrict__ out){
    __shared__ float sh[8];
    __shared__ float bmu, brs;
    long row = blockIdx.x;
    const long MN = (long)NB*HWQ*DIM;
    int c = threadIdx.x;
    float v = p3[row*(long)DIM + c] + p3[MN + row*(long)DIM + c] + b2[c];
    float s = warpRedSum(v);
    if ((c & 31) == 0) sh[c>>5] = s;
    __syncthreads();
    if (c == 0){ float m=0.f; for (int i=0;i<8;i++) m += sh[i]; bmu = m / (float)DIM; }
    __syncthreads();
    float mu = bmu;
    float d = v - mu;
    float vs = warpRedSum(d*d);
    if ((c & 31) == 0) sh[c>>5] = vs;
    __syncthreads();
    if (c == 0){ float m=0.f; for (int i=0;i<8;i++) m += sh[i]; brs = rsqrtf(m/(float)DIM + 1e-5f); }
    __syncthreads();
    float y = d * brs * g[c] + bb[c] + x[row*(long)DIM + c];
    int b = (int)(row / HWQ), p = (int)(row % HWQ);
    out[((long)(b*DIM + c))*HWQ + p] = y;
}

static float* sym(const void* symbol){
    void* p = nullptr;
    cudaGetSymbolAddress(&p, symbol);
    return (float*)p;
}

static GemmP zeroP(){ GemmP p; memset(&p, 0, sizeof(p)); p.D1 = 1; p.SPLIT = 1; return p; }

static void launch_gemm(const GemmP& p, int batches){
    dim3 grid(p.N/64, (p.M+127)/128, batches * p.SPLIT);
    gemm_tc<<<grid, 128>>>(p);
}

extern "C" void kernel_launch(void* const* d_in, const int* in_sizes, int n_in,
                              void* d_out, int out_size){
    const float* q     = (const float*)d_in[0];
    const float* k     = (const float*)d_in[1];
    const float* v     = (const float*)d_in[2];
    const float* Wq    = (const float*)d_in[3];
    const float* bq    = (const float*)d_in[4];
    const float* Wk    = (const float*)d_in[5];
    const float* bk    = (const float*)d_in[6];
    const float* Wv    = (const float*)d_in[7];
    const float* bv    = (const float*)d_in[8];
    const float* Wproj = (const float*)d_in[9];
    const float* bproj = (const float*)d_in[10];
    const float* Waddq = (const float*)d_in[11];
    const float* baddq = (const float*)d_in[12];
    const float* W1    = (const float*)d_in[13];
    const float* b1    = (const float*)d_in[14];
    const float* W2    = (const float*)d_in[15];
    const float* b2    = (const float*)d_in[16];
    const float* g_pre = (const float*)d_in[17];
    const float* b_pre = (const float*)d_in[18];
    const float* g_nrm = (const float*)d_in[19];
    const float* b_nrm = (const float*)d_in[20];
    float* out = (float*)d_out;

    float* kpool = sym(g_kpool);
    float* vpool = sym(g_vpool);
    float* qf    = sym(g_qf);
    float* kf    = sym(g_kf);
    float* vf    = sym(g_vf);
    float* ao    = sym(g_attno);
    float* fac   = sym(g_fac);
    float* lnb   = sym(g_lnbuf);
    float* xb    = sym(g_xbuf);
    float* h1    = sym(g_h1);
    float* part1 = sym(g_part1);
    float* part2 = sym(g_part2);
    float* part3 = sym(g_part3);

    cudaFuncSetAttribute(flash_kernel, cudaFuncAttributeMaxDynamicSharedMemorySize, FL_SMEM);

    {
        long total = (long)NB*NCAM*DIM*PK;
        int blocks = (int)((total + 255) / 256);
        pool_kernel<<<blocks, 256>>>(k, kpool);
        pool_kernel<<<blocks, 256>>>(v, vpool);
    }
    {   // add_q partials: direct q (ATRANS), per-b batch, split-K x3
        GemmP p = zeroP();
        p.A = q; p.ATR = 1; p.lda = HWQ;
        p.a1 = (long)NCAM*DIM*HWQ;
        p.B = Waddq; p.ldb = DIM;
        p.C = part1; p.ldc = DIM; p.c1 = (long)HWQ*DIM;
        p.M = HWQ; p.N = DIM; p.K = ND/3; p.D1 = NB;
        p.SPLIT = 3; p.csplit = (long)NB*HWQ*DIM;
        launch_gemm(p, NB);
    }
    {   // qf per (b,cam): direct q (ATRANS)
        GemmP p = zeroP();
        p.A = q; p.ATR = 1; p.lda = HWQ;
        p.a0 = (long)NCAM*DIM*HWQ; p.a1 = (long)DIM*HWQ;
        p.B = Wq; p.ldb = DIM; p.bias = bq;
        p.C = qf; p.ldc = DIM; p.c0 = (long)NCAM*HWQ*DIM; p.c1 = (long)HWQ*DIM;
        p.M = HWQ; p.N = DIM; p.K = DIM; p.D1 = NCAM;
        launch_gemm(p, NB*NCAM);
    }
    {   // kf, vf per (b,cam): pooled natural layout (ATRANS)
        GemmP p = zeroP();
        p.A = kpool; p.ATR = 1; p.lda = PKP;
        p.a0 = (long)NCAM*DIM*PKP; p.a1 = (long)DIM*PKP;
        p.B = Wk; p.ldb = DIM; p.bias = bk;
        p.C = kf; p.ldc = DIM; p.c0 = (long)NCAM*PK*DIM; p.c1 = (long)PK*DIM;
        p.M = PK; p.N = DIM; p.K = DIM; p.D1 = NCAM;
        launch_gemm(p, NB*NCAM);
        p.A = vpool; p.B = Wv; p.bias = bv; p.C = vf;
        launch_gemm(p, NB*NCAM);
    }
    {   // flash attention, per-cam blocks
        dim3 grid((HWQ+127)/128, NB*NHEAD*NCAM);
        flash_kernel<<<grid, 256, FL_SMEM>>>(qf, kf, vf, ao, fac);
    }
    ln1536_kernel<<<NB*HWQ, 256>>>(ao, fac, g_pre, b_pre, lnb);
    {   // proj partials, split-K x3
        GemmP p = zeroP();
        p.A = lnb; p.lda = ND; p.B = Wproj; p.ldb = DIM;
        p.C = part2; p.ldc = DIM; p.M = NB*HWQ; p.N = DIM;
        p.K = ND/3; p.SPLIT = 3; p.csplit = (long)NB*HWQ*DIM;
        launch_gemm(p, 1);
    }
    {
        long MN = (long)NB*HWQ*DIM;
        reduce_proj_kernel<<<(int)((MN+255)/256), 256>>>(part1, part2, baddq, bproj, xb);
    }
    {   // ffn1 + gelu
        GemmP p = zeroP();
        p.A = xb; p.lda = DIM; p.B = W1; p.ldb = 2*DIM; p.bias = b1; p.gelu = 1;
        p.C = h1; p.ldc = 2*DIM; p.M = NB*HWQ; p.N = 2*DIM; p.K = DIM;
        launch_gemm(p, 1);
    }
    {   // ffn2 partials, split-K x2
        GemmP p = zeroP();
        p.A = h1; p.lda = 2*DIM; p.B = W2; p.ldb = DIM;
        p.C = part3; p.ldc = DIM; p.M = NB*HWQ; p.N = DIM;
        p.K = DIM; p.SPLIT = 2; p.csplit = (long)NB*HWQ*DIM;
        launch_gemm(p, 1);
    }
    final_kernel<<<NB*HWQ, 256>>>(part3, b2, xb, g_nrm, b_nrm, out);
}

// round 13
// speedup vs baseline: 1.0572x; 1.0572x over previous
#include <cuda_runtime.h>
#include <math.h>
#include <string.h>

#define NB    2
#define NCAM  6
#define DIM   256
#define HWQ   2500
#define PK    625
#define PKP   628
#define NHEAD 8
#define DH    32
#define ND    1536

typedef unsigned long long u64;

__device__ __forceinline__ u64 ffma2(u64 a, u64 b, u64 c){
    u64 d; asm("fma.rn.f32x2 %0, %1, %2, %3;" : "=l"(d) : "l"(a), "l"(b), "l"(c)); return d;
}
__device__ __forceinline__ u64 fmul2(u64 a, u64 b){
    u64 d; asm("mul.rn.f32x2 %0, %1, %2;" : "=l"(d) : "l"(a), "l"(b)); return d;
}
__device__ __forceinline__ u64 pack2(float x, float y){
    u64 d; asm("mov.b64 %0, {%1, %2};" : "=l"(d) : "f"(x), "f"(y)); return d;
}
__device__ __forceinline__ float2 unpack2(u64 v){
    float2 r; asm("mov.b64 {%0, %1}, %2;" : "=f"(r.x), "=f"(r.y) : "l"(v)); return r;
}

__device__ float g_kpool [(long)NB*NCAM*DIM*PKP];
__device__ float g_vpool [(long)NB*NCAM*DIM*PKP];
__device__ float g_qf    [(long)NB*NCAM*HWQ*DIM];
__device__ float g_kf    [(long)NB*NCAM*PK*DIM];
__device__ float g_vf    [(long)NB*NCAM*PK*DIM];
__device__ float g_attno [(long)NB*HWQ*ND];
__device__ float g_fac   [(long)NB*HWQ*96];
__device__ float g_lnbuf [(long)NB*HWQ*ND];
__device__ float g_xbuf  [(long)NB*HWQ*DIM];
__device__ float g_h1    [(long)NB*HWQ*2*DIM];
__device__ float g_part1 [(long)3*NB*HWQ*DIM];
__device__ float g_part2 [(long)3*NB*HWQ*DIM];
__device__ float g_part3 [(long)2*NB*HWQ*DIM];

__device__ __forceinline__ float warpRedSum(float v){
    #pragma unroll
    for (int o=16;o;o>>=1) v += __shfl_xor_sync(0xffffffffu, v, o);
    return v;
}

// ---- fused 2x2 pool for K and V, natural (b,cam,c,kk) output ----
__global__ void pool_kernel(const float* __restrict__ ksrc, const float* __restrict__ vsrc,
                            float* __restrict__ kdst, float* __restrict__ vdst){
    long idx = (long)blockIdx.x * blockDim.x + threadIdx.x;
    const long total = (long)NB*NCAM*DIM*PK;
    if (idx >= total) return;
    int kk  = (int)(idx % PK);  long t = idx / PK;
    int c   = (int)(t % DIM);   t /= DIM;
    int cam = (int)(t % NCAM);
    int b   = (int)(t / NCAM);
    int i = kk / 25, j = kk % 25;
    long soff = ((long)((b*NCAM+cam)*DIM + c))*HWQ + (2*i)*50 + 2*j;
    long doff = ((long)((b*NCAM+cam)*DIM + c))*PKP + kk;
    const float* pk = ksrc + soff;
    const float* pv = vsrc + soff;
    kdst[doff] = 0.25f * (pk[0] + pk[1] + pk[50] + pk[51]);
    vdst[doff] = 0.25f * (pv[0] + pv[1] + pv[50] + pv[51]);
}

struct GemmP {
    const float* A; const float* B; const float* bias; float* C;
    int lda, ldb, ldc;
    int M, N, K;
    int gelu, D1, SPLIT, ATR;
    long a0, a1, c0, c1, csplit;
};

__global__ __launch_bounds__(128,4) void gemm_tc(GemmP p){
    __shared__ float As[2][16][128];
    __shared__ float Bs[2][16][64];

    int z = blockIdx.z;
    int s = z % p.SPLIT; int zz = z / p.SPLIT;
    int i1 = zz % p.D1;  int i0 = zz / p.D1;
    long askip = (long)s*p.K*(p.ATR ? (long)p.lda : 1L);
    const float* A = p.A + i0*p.a0 + i1*p.a1 + askip;
    const float* B = p.B + (long)s*p.K*p.ldb;
    float*       C = p.C + i0*p.c0 + i1*p.c1 + (long)s*p.csplit;

    int tid = threadIdx.x;
    int tx = tid & 7, ty = tid >> 3;
    int row0 = blockIdx.y*128, col0 = blockIdx.x*64;

    int arow = row0 + tid;
    bool aok = arow < p.M;
    int brow = tid >> 3;
    int bc0  = (tid & 7) * 2;
    int pb0  = (bc0 ^ (bc0 >> 3)) * 4;
    int pb1  = ((bc0+1) ^ ((bc0+1) >> 3)) * 4;

    u64 acc[8][4];
    #pragma unroll
    for (int i=0;i<8;i++)
        #pragma unroll
        for (int j=0;j<4;j++) acc[i][j] = 0ULL;

    const float4 z4 = make_float4(0.f,0.f,0.f,0.f);
    float av[16]; float4 rb0, rb1;
    const float* atc = p.ATR ? (A + arow) : (A + (aok ? (long)arow*p.lda : 0));

    int nt = p.K / 16;
    if (!p.ATR){
        if (aok){
            float4 r0=*(const float4*)atc, r1=*(const float4*)(atc+4);
            float4 r2=*(const float4*)(atc+8), r3=*(const float4*)(atc+12);
            av[0]=r0.x;av[1]=r0.y;av[2]=r0.z;av[3]=r0.w;
            av[4]=r1.x;av[5]=r1.y;av[6]=r1.z;av[7]=r1.w;
            av[8]=r2.x;av[9]=r2.y;av[10]=r2.z;av[11]=r2.w;
            av[12]=r3.x;av[13]=r3.y;av[14]=r3.z;av[15]=r3.w;
        } else {
            #pragma unroll
            for (int j=0;j<16;j++) av[j]=0.f;
        }
    } else {
        #pragma unroll
        for (int j=0;j<16;j++) av[j] = aok ? atc[(long)j*p.lda] : 0.f;
    }
    {
        const float* pb = B + (long)brow*p.ldb + col0 + bc0*4;
        rb0 = *(const float4*)pb; rb1 = *(const float4*)(pb+4);
    }
    {
        #pragma unroll
        for (int j=0;j<16;j++) As[0][j][tid]=av[j];
        *(float4*)&Bs[0][brow][pb0] = rb0;
        *(float4*)&Bs[0][brow][pb1] = rb1;
    }
    __syncthreads();
    int cur = 0;
    for (int t=0; t<nt; t++){
        if (t+1 < nt){
            int k0 = (t+1)*16;
            if (!p.ATR){
                if (aok){
                    const float* pa = atc + k0;
                    float4 r0=*(const float4*)pa, r1=*(const float4*)(pa+4);
                    float4 r2=*(const float4*)(pa+8), r3=*(const float4*)(pa+12);
                    av[0]=r0.x;av[1]=r0.y;av[2]=r0.z;av[3]=r0.w;
                    av[4]=r1.x;av[5]=r1.y;av[6]=r1.z;av[7]=r1.w;
                    av[8]=r2.x;av[9]=r2.y;av[10]=r2.z;av[11]=r2.w;
                    av[12]=r3.x;av[13]=r3.y;av[14]=r3.z;av[15]=r3.w;
                }
            } else {
                #pragma unroll
                for (int j=0;j<16;j++) av[j] = aok ? atc[(long)(k0+j)*p.lda] : 0.f;
            }
            const float* pb = B + (long)(k0+brow)*p.ldb + col0 + bc0*4;
            rb0 = *(const float4*)pb; rb1 = *(const float4*)(pb+4);
        }
        #pragma unroll
        for (int kk=0; kk<16; kk++){
            float4 a0 = *(const float4*)&As[cur][kk][ty*8];
            float4 a1 = *(const float4*)&As[cur][kk][ty*8+4];
            ulonglong2 b0 = *(const ulonglong2*)&Bs[cur][kk][pb0];
            ulonglong2 b1 = *(const ulonglong2*)&Bs[cur][kk][pb1];
            u64 ap;
            ap=pack2(a0.x,a0.x); acc[0][0]=ffma2(ap,b0.x,acc[0][0]); acc[0][1]=ffma2(ap,b0.y,acc[0][1]); acc[0][2]=ffma2(ap,b1.x,acc[0][2]); acc[0][3]=ffma2(ap,b1.y,acc[0][3]);
            ap=pack2(a0.y,a0.y); acc[1][0]=ffma2(ap,b0.x,acc[1][0]); acc[1][1]=ffma2(ap,b0.y,acc[1][1]); acc[1][2]=ffma2(ap,b1.x,acc[1][2]); acc[1][3]=ffma2(ap,b1.y,acc[1][3]);
            ap=pack2(a0.z,a0.z); acc[2][0]=ffma2(ap,b0.x,acc[2][0]); acc[2][1]=ffma2(ap,b0.y,acc[2][1]); acc[2][2]=ffma2(ap,b1.x,acc[2][2]); acc[2][3]=ffma2(ap,b1.y,acc[2][3]);
            ap=pack2(a0.w,a0.w); acc[3][0]=ffma2(ap,b0.x,acc[3][0]); acc[3][1]=ffma2(ap,b0.y,acc[3][1]); acc[3][2]=ffma2(ap,b1.x,acc[3][2]); acc[3][3]=ffma2(ap,b1.y,acc[3][3]);
            ap=pack2(a1.x,a1.x); acc[4][0]=ffma2(ap,b0.x,acc[4][0]); acc[4][1]=ffma2(ap,b0.y,acc[4][1]); acc[4][2]=ffma2(ap,b1.x,acc[4][2]); acc[4][3]=ffma2(ap,b1.y,acc[4][3]);
            ap=pack2(a1.y,a1.y); acc[5][0]=ffma2(ap,b0.x,acc[5][0]); acc[5][1]=ffma2(ap,b0.y,acc[5][1]); acc[5][2]=ffma2(ap,b1.x,acc[5][2]); acc[5][3]=ffma2(ap,b1.y,acc[5][3]);
            ap=pack2(a1.z,a1.z); acc[6][0]=ffma2(ap,b0.x,acc[6][0]); acc[6][1]=ffma2(ap,b0.y,acc[6][1]); acc[6][2]=ffma2(ap,b1.x,acc[6][2]); acc[6][3]=ffma2(ap,b1.y,acc[6][3]);
            ap=pack2(a1.w,a1.w); acc[7][0]=ffma2(ap,b0.x,acc[7][0]); acc[7][1]=ffma2(ap,b0.y,acc[7][1]); acc[7][2]=ffma2(ap,b1.x,acc[7][2]); acc[7][3]=ffma2(ap,b1.y,acc[7][3]);
        }
        if (t+1 < nt){
            int nb = cur ^ 1;
            #pragma unroll
            for (int j=0;j<16;j++) As[nb][j][tid]=av[j];
            *(float4*)&Bs[nb][brow][pb0] = rb0;
            *(float4*)&Bs[nb][brow][pb1] = rb1;
            __syncthreads();
            cur = nb;
        }
    }
    int colb = col0 + tx*8;
    float4 bia0, bia1;
    if (p.SPLIT == 1 && p.bias){
        bia0 = *(const float4*)(p.bias + colb);
        bia1 = *(const float4*)(p.bias + colb + 4);
    } else { bia0 = z4; bia1 = z4; }
    #pragma unroll
    for (int i=0;i<8;i++){
        int r = row0 + ty*8 + i;
        if (r >= p.M) continue;
        float2 v0 = unpack2(acc[i][0]), v1 = unpack2(acc[i][1]);
        float2 v2 = unpack2(acc[i][2]), v3 = unpack2(acc[i][3]);
        float4 o0 = make_float4(v0.x+bia0.x, v0.y+bia0.y, v1.x+bia0.z, v1.y+bia0.w);
        float4 o1 = make_float4(v2.x+bia1.x, v2.y+bia1.y, v3.x+bia1.z, v3.y+bia1.w);
        if (p.gelu){
            o0.x*=normcdff(o0.x); o0.y*=normcdff(o0.y); o0.z*=normcdff(o0.z); o0.w*=normcdff(o0.w);
            o1.x*=normcdff(o1.x); o1.y*=normcdff(o1.y); o1.z*=normcdff(o1.z); o1.w*=normcdff(o1.w);
        }
        *(float4*)(C + (long)r*p.ldc + colb)     = o0;
        *(float4*)(C + (long)r*p.ldc + colb + 4) = o1;
    }
}

// ---- flash attention (R10 proven): per-(b,head,cam) blocks, q-tile 128 ----
#define QS_OFF 0
#define KS_OFF 4096
#define VT_OFF 8704
#define PS_OFF 13056
#define CS_OFF 21760
#define FL_SMEM (21888*4)

__global__ __launch_bounds__(256,1) void flash_kernel(
    const float* __restrict__ qf, const float* __restrict__ kf,
    const float* __restrict__ vf, float* __restrict__ ao, float* __restrict__ fac)
{
    extern __shared__ float sm[];
    float* Qs    = sm + QS_OFF;
    float* KsB   = sm + KS_OFF;
    float* VtB   = sm + VT_OFF;
    float* Ps    = sm + PS_OFF;
    float* corrS = sm + CS_OFF;

    int yy = blockIdx.y;
    int cam = yy % 6; int bm = yy / 6; int b = bm >> 3, m = bm & 7;
    int q0 = blockIdx.x * 128;
    int tid = threadIdx.x;

    int kg = tid & 15, rg = tid >> 4;
    int rgx = (rg & 1) << 4;
    int ks = tid >> 7, low = tid & 127;
    int orow = low >> 3, oc = low & 7;
    int orx = (orow & 1) << 4;
    int qr = tid >> 1, qh = tid & 1;
    int fr = tid >> 2, fq = tid & 3;

    const float scale = 0.17677669529663689f;
    const float4 z4 = make_float4(0.f,0.f,0.f,0.f);

    const float* qb = qf + ((long)(b*NCAM+cam)*HWQ)*DIM + m*DH;
    const float* kb = kf + ((long)(b*NCAM+cam)*PK)*DIM + m*DH;
    const float* vb = vf + ((long)(b*NCAM+cam)*PK)*DIM + m*DH;

    {
        bool qok = (q0 + qr) < HWQ;
        const float* qp = qb + (long)(q0+qr)*DIM + qh*16;
        float4 q0r = qok ? *(const float4*)(qp)     : z4;
        float4 q1r = qok ? *(const float4*)(qp + 4) : z4;
        float4 q2r = qok ? *(const float4*)(qp + 8) : z4;
        float4 q3r = qok ? *(const float4*)(qp +12) : z4;
        float4 kr0 = *(const float4*)(kb + (long)fr*DIM + fq*8);
        float4 kr1 = *(const float4*)(kb + (long)fr*DIM + fq*8 + 4);
        float4 vr0 = *(const float4*)(vb + (long)fr*DIM + fq*8);
        float4 vr1 = *(const float4*)(vb + (long)fr*DIM + fq*8 + 4);
        int rl = qr & 7;
        q0r.x*=scale; q0r.y*=scale; q0r.z*=scale; q0r.w*=scale;
        q1r.x*=scale; q1r.y*=scale; q1r.z*=scale; q1r.w*=scale;
        q2r.x*=scale; q2r.y*=scale; q2r.z*=scale; q2r.w*=scale;
        q3r.x*=scale; q3r.y*=scale; q3r.z*=scale; q3r.w*=scale;
        *(float4*)(Qs + qr*32 + (((qh*4+0)^rl)<<2)) = q0r;
        *(float4*)(Qs + qr*32 + (((qh*4+1)^rl)<<2)) = q1r;
        *(float4*)(Qs + qr*32 + (((qh*4+2)^rl)<<2)) = q2r;
        *(float4*)(Qs + qr*32 + (((qh*4+3)^rl)<<2)) = q3r;
        *(float4*)(KsB + fr*36 + fq*8)     = kr0;
        *(float4*)(KsB + fr*36 + fq*8 + 4) = kr1;
        VtB[(fq*8+0)*68 + fr] = vr0.x; VtB[(fq*8+1)*68 + fr] = vr0.y;
        VtB[(fq*8+2)*68 + fr] = vr0.z; VtB[(fq*8+3)*68 + fr] = vr0.w;
        VtB[(fq*8+4)*68 + fr] = vr1.x; VtB[(fq*8+5)*68 + fr] = vr1.y;
        VtB[(fq*8+6)*68 + fr] = vr1.z; VtB[(fq*8+7)*68 + fr] = vr1.w;
    }
    __syncthreads();

    float mrow[8], lrow[8];
    #pragma unroll
    for (int i=0;i<8;i++){ mrow[i] = -1e30f; lrow[i] = 0.f; }
    u64 acc[8][4];
    #pragma unroll
    for (int i=0;i<8;i++)
        #pragma unroll
        for (int s=0;s<4;s++) acc[i][s] = 0ULL;

    float4 kr0, kr1, vr0, vr1;
    for (int kt=0; kt<10; kt++){
        int cur = kt & 1;
        if (kt < 9){
            int kn = (kt+1)*64;
            bool ok = (kn + fr) < PK;
            const float* kp = kb + (long)(kn+fr)*DIM + fq*8;
            const float* vp = vb + (long)(kn+fr)*DIM + fq*8;
            kr0 = ok ? *(const float4*)kp     : z4;
            kr1 = ok ? *(const float4*)(kp+4) : z4;
            vr0 = ok ? *(const float4*)vp     : z4;
            vr1 = ok ? *(const float4*)(vp+4) : z4;
        }
        u64 sacc[8][4];
        #pragma unroll
        for (int i=0;i<8;i++)
            #pragma unroll
            for (int j=0;j<4;j++) sacc[i][j] = 0ULL;
        const float* Kc = KsB + cur*2304;
        #pragma unroll
        for (int c4=0;c4<8;c4++){
            ulonglong2 kv[4];
            #pragma unroll
            for (int j=0;j<4;j++)
                kv[j] = *(const ulonglong2*)(Kc + (kg+16*j)*36 + c4*4);
            #pragma unroll
            for (int i=0;i<8;i++){
                ulonglong2 qv = *(const ulonglong2*)(Qs + (rg*8+i)*32 + ((c4 ^ i)<<2));
                #pragma unroll
                for (int j=0;j<4;j++){
                    sacc[i][j] = ffma2(qv.x, kv[j].x, sacc[i][j]);
                    sacc[i][j] = ffma2(qv.y, kv[j].y, sacc[i][j]);
                }
            }
        }
        int kk0 = kt*64;
        #pragma unroll
        for (int i=0;i<8;i++){
            float s_[4]; float tmax = -1e30f;
            #pragma unroll
            for (int j=0;j<4;j++){
                float2 t2 = unpack2(sacc[i][j]);
                float v = t2.x + t2.y;
                if (kk0 + kg + 16*j >= PK) v = -1e30f;
                s_[j] = v; tmax = fmaxf(tmax, v);
            }
            #pragma unroll
            for (int off=1; off<16; off<<=1)
                tmax = fmaxf(tmax, __shfl_xor_sync(0xffffffffu, tmax, off));
            float mnew = fmaxf(mrow[i], tmax);
            float corr = __expf(mrow[i] - mnew);
            float rsum = 0.f;
            #pragma unroll
            for (int j=0;j<4;j++){
                float pv = __expf(s_[j] - mnew);
                rsum += pv;
                Ps[(rg*8+i)*68 + ((kg + 16*j) ^ rgx)] = pv;
            }
            #pragma unroll
            for (int off=1; off<16; off<<=1)
                rsum += __shfl_xor_sync(0xffffffffu, rsum, off);
            lrow[i] = lrow[i]*corr + rsum;
            mrow[i] = mnew;
            if (kg == 0) corrS[rg*8+i] = corr;
        }
        __syncthreads();
        #pragma unroll
        for (int i=0;i<8;i++){
            float c = corrS[orow*8+i];
            u64 cp = pack2(c, c);
            #pragma unroll
            for (int s=0;s<4;s++) acc[i][s] = fmul2(acc[i][s], cp);
        }
        const float* Vc = VtB + cur*2176;
        #pragma unroll
        for (int t=0;t<8;t++){
            int k4 = (ks*8 + t)*4;
            ulonglong2 vv[4];
            #pragma unroll
            for (int s=0;s<4;s++)
                vv[s] = *(const ulonglong2*)(Vc + (oc+8*s)*68 + k4);
            #pragma unroll
            for (int i=0;i<8;i++){
                ulonglong2 pp = *(const ulonglong2*)(Ps + (orow*8+i)*68 + (k4 ^ orx));
                #pragma unroll
                for (int s=0;s<4;s++){
                    acc[i][s] = ffma2(pp.x, vv[s].x, acc[i][s]);
                    acc[i][s] = ffma2(pp.y, vv[s].y, acc[i][s]);
                }
            }
        }
        if (kt < 9){
            int nb = cur ^ 1;
            *(float4*)(KsB + nb*2304 + fr*36 + fq*8)     = kr0;
            *(float4*)(KsB + nb*2304 + fr*36 + fq*8 + 4) = kr1;
            float* Vn = VtB + nb*2176;
            Vn[(fq*8+0)*68 + fr] = vr0.x; Vn[(fq*8+1)*68 + fr] = vr0.y;
            Vn[(fq*8+2)*68 + fr] = vr0.z; Vn[(fq*8+3)*68 + fr] = vr0.w;
            Vn[(fq*8+4)*68 + fr] = vr1.x; Vn[(fq*8+5)*68 + fr] = vr1.y;
            Vn[(fq*8+6)*68 + fr] = vr1.z; Vn[(fq*8+7)*68 + fr] = vr1.w;
        }
        __syncthreads();
    }

    float o[8][4];
    #pragma unroll
    for (int i=0;i<8;i++)
        #pragma unroll
        for (int s=0;s<4;s++){
            float2 t = unpack2(acc[i][s]);
            o[i][s] = t.x + t.y;
        }
    if (ks == 1){
        #pragma unroll
        for (int i=0;i<8;i++)
            #pragma unroll
            for (int s=0;s<4;s++)
                Ps[(orow*8+i)*33 + oc + 8*s] = o[i][s];
    }
    __syncthreads();
    if (ks == 0){
        #pragma unroll
        for (int i=0;i<8;i++){
            int qq = q0 + orow*8 + i;
            if (qq >= HWQ) continue;
            long base = ((long)b*HWQ + qq)*ND + cam*DIM + m*DH;
            #pragma unroll
            for (int s=0;s<4;s++)
                ao[base + oc + 8*s] = o[i][s] + Ps[(orow*8+i)*33 + oc + 8*s];
        }
    }
    if (kg == 0){
        #pragma unroll
        for (int i=0;i<8;i++){
            int qq = q0 + rg*8 + i;
            if (qq >= HWQ) continue;
            long f0 = ((long)b*HWQ + qq)*96;
            fac[f0 + cam*8 + m]      = mrow[i];
            fac[f0 + 48 + cam*8 + m] = lrow[i];
        }
    }
}

__global__ void ln1536_kernel(const float* __restrict__ x, const float* __restrict__ fac,
                              const float* __restrict__ g, const float* __restrict__ b,
                              float* __restrict__ y){
    __shared__ float sh[8];
    __shared__ float bmu, brs;
    __shared__ float f48[48];
    long row = blockIdx.x;
    const float* p = x + row * (long)ND;
    const float* fr = fac + row * 96;
    int tid = threadIdx.x;
    if (tid < 48){
        int mm = tid & 7;
        float mx = fr[mm];
        #pragma unroll
        for (int c=1;c<6;c++) mx = fmaxf(mx, fr[c*8+mm]);
        float den = 0.f;
        #pragma unroll
        for (int c=0;c<6;c++) den += fr[48+c*8+mm] * __expf(fr[c*8+mm]-mx);
        f48[tid] = __expf(fr[tid]-mx) / den;
    }
    __syncthreads();
    float vals[6]; float s = 0.f;
    #pragma unroll
    for (int i=0;i<6;i++){
        int c = tid + i*256;
        float fv = f48[((c>>8)<<3) + ((c>>5)&7)];
        vals[i] = p[c] * fv; s += vals[i];
    }
    s = warpRedSum(s);
    if ((tid & 31) == 0) sh[tid>>5] = s;
    __syncthreads();
    if (tid == 0){ float t=0.f; for (int i=0;i<8;i++) t += sh[i]; bmu = t / (float)ND; }
    __syncthreads();
    float mu = bmu, vs = 0.f;
    #pragma unroll
    for (int i=0;i<6;i++){ float d = vals[i]-mu; vs += d*d; }
    vs = warpRedSum(vs);
    if ((tid & 31) == 0) sh[tid>>5] = vs;
    __syncthreads();
    if (tid == 0){ float t=0.f; for (int i=0;i<8;i++) t += sh[i]; brs = rsqrtf(t/(float)ND + 1e-5f); }
    __syncthreads();
    float rs = brs;
    float* q = y + row * (long)ND;
    #pragma unroll
    for (int i=0;i<6;i++){ int c = tid + i*256; q[c] = (vals[i]-mu)*rs*g[c] + b[c]; }
}

// ---- vectorized proj reduce ----
__global__ void reduce_proj_kernel(const float* __restrict__ p1, const float* __restrict__ p2,
                                   const float* __restrict__ baddq, const float* __restrict__ bproj,
                                   float* __restrict__ xb){
    long i4 = (long)blockIdx.x * 256 + threadIdx.x;
    const long MN4 = (long)NB*HWQ*DIM/4;
    if (i4 >= MN4) return;
    int c4 = (int)(i4 & 63);
    float4 bb1 = *(const float4*)(baddq + c4*4);
    float4 bb2 = *(const float4*)(bproj + c4*4);
    float4 a0 = *(const float4*)(p1 + i4*4);
    float4 a1 = *(const float4*)(p1 + (i4+MN4)*4);
    float4 a2 = *(const float4*)(p1 + (i4+2*MN4)*4);
    float4 b0 = *(const float4*)(p2 + i4*4);
    float4 b1 = *(const float4*)(p2 + (i4+MN4)*4);
    float4 b2 = *(const float4*)(p2 + (i4+2*MN4)*4);
    float4 o;
    o.x = bb1.x+bb2.x + a0.x+a1.x+a2.x + b0.x+b1.x+b2.x;
    o.y = bb1.y+bb2.y + a0.y+a1.y+a2.y + b0.y+b1.y+b2.y;
    o.z = bb1.z+bb2.z + a0.z+a1.z+a2.z + b0.z+b1.z+b2.z;
    o.w = bb1.w+bb2.w + a0.w+a1.w+a2.w + b0.w+b1.w+b2.w;
    *(float4*)(xb + i4*4) = o;
}

// ---- final: LN(sum p3 + b2) + x, direct transposed store ----
__global__ void final_kernel(const float* __restrict__ p3, const float* __restrict__ b2,
                             const float* __restrict__ x,
                             const float* __restrict__ g, const float* __restrict__ bb,
                             float* __restrict__ out){
    __shared__ float sh[8];
    __shared__ float bmu, brs;
    long row = blockIdx.x;
    const long MN = (long)NB*HWQ*DIM;
    int c = threadIdx.x;
    float v = p3[row*(long)DIM + c] + p3[MN + row*(long)DIM + c] + b2[c];
    float s = warpRedSum(v);
    if ((c & 31) == 0) sh[c>>5] = s;
    __syncthreads();
    if (c == 0){ float m=0.f; for (int i=0;i<8;i++) m += sh[i]; bmu = m / (float)DIM; }
    __syncthreads();
    float mu = bmu;
    float d = v - mu;
    float vs = warpRedSum(d*d);
    if ((c & 31) == 0) sh[c>>5] = vs;
    __syncthreads();
    if (c == 0){ float m=0.f; for (int i=0;i<8;i++) m += sh[i]; brs = rsqrtf(m/(float)DIM + 1e-5f); }
    __syncthreads();
    float y = d * brs * g[c] + bb[c] + x[row*(long)DIM + c];
    int b = (int)(row / HWQ), p = (int)(row % HWQ);
    out[((long)(b*DIM + c))*HWQ + p] = y;
}

static float* sym(const void* symbol){
    void* p = nullptr;
    cudaGetSymbolAddress(&p, symbol);
    return (float*)p;
}

static GemmP zeroP(){ GemmP p; memset(&p, 0, sizeof(p)); p.D1 = 1; p.SPLIT = 1; return p; }

static void launch_gemm(const GemmP& p, int batches){
    dim3 grid(p.N/64, (p.M+127)/128, batches * p.SPLIT);
    gemm_tc<<<grid, 128>>>(p);
}

extern "C" void kernel_launch(void* const* d_in, const int* in_sizes, int n_in,
                              void* d_out, int out_size){
    const float* q     = (const float*)d_in[0];
    const float* k     = (const float*)d_in[1];
    const float* v     = (const float*)d_in[2];
    const float* Wq    = (const float*)d_in[3];
    const float* bq    = (const float*)d_in[4];
    const float* Wk    = (const float*)d_in[5];
    const float* bk    = (const float*)d_in[6];
    const float* Wv    = (const float*)d_in[7];
    const float* bv    = (const float*)d_in[8];
    const float* Wproj = (const float*)d_in[9];
    const float* bproj = (const float*)d_in[10];
    const float* Waddq = (const float*)d_in[11];
    const float* baddq = (const float*)d_in[12];
    const float* W1    = (const float*)d_in[13];
    const float* b1    = (const float*)d_in[14];
    const float* W2    = (const float*)d_in[15];
    const float* b2    = (const float*)d_in[16];
    const float* g_pre = (const float*)d_in[17];
    const float* b_pre = (const float*)d_in[18];
    const float* g_nrm = (const float*)d_in[19];
    const float* b_nrm = (const float*)d_in[20];
    float* out = (float*)d_out;

    float* kpool = sym(g_kpool);
    float* vpool = sym(g_vpool);
    float* qf    = sym(g_qf);
    float* kf    = sym(g_kf);
    float* vf    = sym(g_vf);
    float* ao    = sym(g_attno);
    float* fac   = sym(g_fac);
    float* lnb   = sym(g_lnbuf);
    float* xb    = sym(g_xbuf);
    float* h1    = sym(g_h1);
    float* part1 = sym(g_part1);
    float* part2 = sym(g_part2);
    float* part3 = sym(g_part3);

    cudaFuncSetAttribute(flash_kernel, cudaFuncAttributeMaxDynamicSharedMemorySize, FL_SMEM);

    {   // fused pool k+v
        long total = (long)NB*NCAM*DIM*PK;
        int blocks = (int)((total + 255) / 256);
        pool_kernel<<<blocks, 256>>>(k, v, kpool, vpool);
    }
    {   // add_q partials: direct q (ATRANS), per-b batch, split-K x3
        GemmP p = zeroP();
        p.A = q; p.ATR = 1; p.lda = HWQ;
        p.a1 = (long)NCAM*DIM*HWQ;
        p.B = Waddq; p.ldb = DIM;
        p.C = part1; p.ldc = DIM; p.c1 = (long)HWQ*DIM;
        p.M = HWQ; p.N = DIM; p.K = ND/3; p.D1 = NB;
        p.SPLIT = 3; p.csplit = (long)NB*HWQ*DIM;
        launch_gemm(p, NB);
    }
    {   // qf per (b,cam): direct q (ATRANS)
        GemmP p = zeroP();
        p.A = q; p.ATR = 1; p.lda = HWQ;
        p.a0 = (long)NCAM*DIM*HWQ; p.a1 = (long)DIM*HWQ;
        p.B = Wq; p.ldb = DIM; p.bias = bq;
        p.C = qf; p.ldc = DIM; p.c0 = (long)NCAM*HWQ*DIM; p.c1 = (long)HWQ*DIM;
        p.M = HWQ; p.N = DIM; p.K = DIM; p.D1 = NCAM;
        launch_gemm(p, NB*NCAM);
    }
    {   // kf, vf per (b,cam): pooled natural layout (ATRANS)
        GemmP p = zeroP();
        p.A = kpool; p.ATR = 1; p.lda = PKP;
        p.a0 = (long)NCAM*DIM*PKP; p.a1 = (long)DIM*PKP;
        p.B = Wk; p.ldb = DIM; p.bias = bk;
        p.C = kf; p.ldc = DIM; p.c0 = (long)NCAM*PK*DIM; p.c1 = (long)PK*DIM;
        p.M = PK; p.N = DIM; p.K = DIM; p.D1 = NCAM;
        launch_gemm(p, NB*NCAM);
        p.A = vpool; p.B = Wv; p.bias = bv; p.C = vf;
        launch_gemm(p, NB*NCAM);
    }
    {   // flash attention, per-cam blocks
        dim3 grid((HWQ+127)/128, NB*NHEAD*NCAM);
        flash_kernel<<<grid, 256, FL_SMEM>>>(qf, kf, vf, ao, fac);
    }
    ln1536_kernel<<<NB*HWQ, 256>>>(ao, fac, g_pre, b_pre, lnb);
    {   // proj partials, split-K x3
        GemmP p = zeroP();
        p.A = lnb; p.lda = ND; p.B = Wproj; p.ldb = DIM;
        p.C = part2; p.ldc = DIM; p.M = NB*HWQ; p.N = DIM;
        p.K = ND/3; p.SPLIT = 3; p.csplit = (long)NB*HWQ*DIM;
        launch_gemm(p, 1);
    }
    {
        long MN4 = (long)NB*HWQ*DIM/4;
        reduce_proj_kernel<<<(int)((MN4+255)/256), 256>>>(part1, part2, baddq, bproj, xb);
    }
    {   // ffn1 + gelu
        GemmP p = zeroP();
        p.A = xb; p.lda = DIM; p.B = W1; p.ldb = 2*DIM; p.bias = b1; p.gelu = 1;
        p.C = h1; p.ldc = 2*DIM; p.M = NB*HWQ; p.N = 2*DIM; p.K = DIM;
        launch_gemm(p, 1);
    }
    {   // ffn2 partials, split-K x2
        GemmP p = zeroP();
        p.A = h1; p.lda = 2*DIM; p.B = W2; p.ldb = DIM;
        p.C = part3; p.ldc = DIM; p.M = NB*HWQ; p.N = DIM;
        p.K = DIM; p.SPLIT = 2; p.csplit = (long)NB*HWQ*DIM;
        launch_gemm(p, 1);
    }
    final_kernel<<<NB*HWQ, 256>>>(part3, b2, xb, g_nrm, b_nrm, out);
}